// round 1
// baseline (speedup 1.0000x reference)
#include <cuda_runtime.h>
#include <cuda_bf16.h>

#define BATCH 16
#define CIN   256
#define NPIX  4096   // 64*64
#define M3    768    // 3*256 combined qkv channels

// Scratch for Q/K/V conv outputs: [B][768][4096] (q: rows 0-255, k: 256-511, v: 512-767)
__device__ float g_qkv[(size_t)BATCH * M3 * NPIX];

// ---------------------------------------------------------------------------
// Kernel 1: fused QKV 1x1 conv as SGEMM.
// out[b, o', p] = sum_c w_region[o_local, c] * x[b, c, p] + bias_region[o_local]
// Block: 64 (channels) x 64 (pixels) tile, BK=16, 256 threads, 4x4 microtile.
// ---------------------------------------------------------------------------
__global__ __launch_bounds__(256) void qkv_gemm_kernel(
    const float* __restrict__ x,
    const float* __restrict__ wq, const float* __restrict__ bq,
    const float* __restrict__ wk, const float* __restrict__ bk,
    const float* __restrict__ wv, const float* __restrict__ bv)
{
    __shared__ float As[16][68];   // [c][o] transposed weight tile
    __shared__ float Bs[16][68];   // [c][p] x tile

    const int b      = blockIdx.z;
    const int ytile  = blockIdx.y;          // 0..11
    const int p0     = blockIdx.x * 64;
    const int region = ytile >> 2;          // 0:q 1:k 2:v
    const int oL0    = (ytile & 3) * 64;    // local (within-region) channel tile base

    const float* w    = (region == 0) ? wq : (region == 1) ? wk : wv;
    const float* bias = (region == 0) ? bq : (region == 1) ? bk : bv;

    const int t  = threadIdx.x;
    const int tx = t & 15;          // pixel microtile
    const int ty = t >> 4;          // channel microtile
    const int a_row = t >> 2;       // 0..63 channel offset in tile
    const int a_col = (t & 3) << 2; // 0..12 k offset
    const int b_row = t >> 4;       // 0..15 k offset
    const int b_col = (t & 15) << 2;// 0..60 pixel offset

    const float* xb = x + (size_t)b * CIN * NPIX;

    float acc[4][4] = {};
    for (int c0 = 0; c0 < CIN; c0 += 16) {
        float4 av  = *(const float4*)(w + (size_t)(oL0 + a_row) * CIN + c0 + a_col);
        float4 bvv = *(const float4*)(xb + (size_t)(c0 + b_row) * NPIX + p0 + b_col);
        __syncthreads();
        As[a_col + 0][a_row] = av.x;
        As[a_col + 1][a_row] = av.y;
        As[a_col + 2][a_row] = av.z;
        As[a_col + 3][a_row] = av.w;
        *(float4*)(&Bs[b_row][b_col]) = bvv;
        __syncthreads();
#pragma unroll
        for (int k = 0; k < 16; k++) {
            float4 a  = *(const float4*)(&As[k][ty * 4]);
            float4 bb = *(const float4*)(&Bs[k][tx * 4]);
            float ar[4] = {a.x, a.y, a.z, a.w};
            float br[4] = {bb.x, bb.y, bb.z, bb.w};
#pragma unroll
            for (int i = 0; i < 4; i++)
#pragma unroll
                for (int j = 0; j < 4; j++)
                    acc[i][j] = fmaf(ar[i], br[j], acc[i][j]);
        }
    }

    float* outp = g_qkv + ((size_t)b * M3 + (size_t)ytile * 64) * NPIX;
#pragma unroll
    for (int i = 0; i < 4; i++) {
        int rowInTile = ty * 4 + i;
        float bi = bias[oL0 + rowInTile];
        float4 v;
        v.x = acc[i][0] + bi;
        v.y = acc[i][1] + bi;
        v.z = acc[i][2] + bi;
        v.w = acc[i][3] + bi;
        *(float4*)(outp + (size_t)rowInTile * NPIX + p0 + tx * 4) = v;
    }
}

// ---------------------------------------------------------------------------
// Kernel 2: per-(batch, channel) attention on [64,64] tiles.
// S = Q K^T / sqrt(32); P = softmax_row(S); ctx = P V
// One block per (b, o). 256 threads, 4x4 microtiles for both matmuls.
// Shared memory reused: X1 = qT then P^T(g,h); X2 = kT then V(g,w).
// ---------------------------------------------------------------------------
__global__ __launch_bounds__(256) void attn_kernel(float* __restrict__ out)
{
    __shared__ float X1[64][68];   // qT[w][h]  -> later Ps[g][h]
    __shared__ float X2[64][68];   // kT[w][g]  -> later Vs[g][w]

    const int blk = blockIdx.x;
    const int b   = blk >> 8;
    const int o   = blk & 255;

    const float* qp = g_qkv + ((size_t)b * M3 + o) * NPIX;
    const float* kp = qp + (size_t)256 * NPIX;
    const float* vp = qp + (size_t)512 * NPIX;

    const int t  = threadIdx.x;
    const int tx = t & 15;
    const int ty = t >> 4;

    // Load q,k transposed into smem; prefetch v into registers.
    float4 vr[4];
#pragma unroll
    for (int it = 0; it < 4; it++) {
        int flat = t * 4 + it * 1024;
        int h = flat >> 6, wcol = flat & 63;
        float4 qv = *(const float4*)(qp + flat);
        float4 kv = *(const float4*)(kp + flat);
        vr[it]    = *(const float4*)(vp + flat);
        X1[wcol + 0][h] = qv.x; X1[wcol + 1][h] = qv.y;
        X1[wcol + 2][h] = qv.z; X1[wcol + 3][h] = qv.w;
        X2[wcol + 0][h] = kv.x; X2[wcol + 1][h] = kv.y;
        X2[wcol + 2][h] = kv.z; X2[wcol + 3][h] = kv.w;
    }
    __syncthreads();

    // S[h][g] = sum_w qT[w][h] * kT[w][g]
    float s[4][4] = {};
#pragma unroll 8
    for (int w = 0; w < 64; w++) {
        float4 a  = *(const float4*)(&X1[w][ty * 4]);
        float4 bb = *(const float4*)(&X2[w][tx * 4]);
        float ar[4] = {a.x, a.y, a.z, a.w};
        float br[4] = {bb.x, bb.y, bb.z, bb.w};
#pragma unroll
        for (int i = 0; i < 4; i++)
#pragma unroll
            for (int j = 0; j < 4; j++)
                s[i][j] = fmaf(ar[i], br[j], s[i][j]);
    }

    // Softmax over g. Row h = ty*4+i owned by the 16 lanes sharing ty
    // (lanes [0..15]/[16..31] of each warp -> width-16 shuffle groups align).
    const float scale = 0.17677669529663687f;  // 1/sqrt(32)
#pragma unroll
    for (int i = 0; i < 4; i++) {
        float m = -1e30f;
#pragma unroll
        for (int j = 0; j < 4; j++) { s[i][j] *= scale; m = fmaxf(m, s[i][j]); }
#pragma unroll
        for (int off = 8; off > 0; off >>= 1)
            m = fmaxf(m, __shfl_xor_sync(0xffffffffu, m, off, 16));
        float sum = 0.f;
#pragma unroll
        for (int j = 0; j < 4; j++) { s[i][j] = __expf(s[i][j] - m); sum += s[i][j]; }
#pragma unroll
        for (int off = 8; off > 0; off >>= 1)
            sum += __shfl_xor_sync(0xffffffffu, sum, off, 16);
        float inv = 1.f / sum;
#pragma unroll
        for (int j = 0; j < 4; j++) s[i][j] *= inv;
    }

    __syncthreads();   // all scores reads of X1/X2 done

    // X1 <- P transposed as Ps[g][h]; X2 <- V natural layout Vs[g][w]
#pragma unroll
    for (int i = 0; i < 4; i++)
#pragma unroll
        for (int j = 0; j < 4; j++)
            X1[tx * 4 + j][ty * 4 + i] = s[i][j];
#pragma unroll
    for (int it = 0; it < 4; it++) {
        int flat = t * 4 + it * 1024;
        int g = flat >> 6, wcol = flat & 63;
        *(float4*)(&X2[g][wcol]) = vr[it];
    }
    __syncthreads();

    // ctx[h][w] = sum_g Ps[g][h] * Vs[g][w]
    float c[4][4] = {};
#pragma unroll 8
    for (int g = 0; g < 64; g++) {
        float4 a  = *(const float4*)(&X1[g][ty * 4]);
        float4 bb = *(const float4*)(&X2[g][tx * 4]);
        float ar[4] = {a.x, a.y, a.z, a.w};
        float br[4] = {bb.x, bb.y, bb.z, bb.w};
#pragma unroll
        for (int i = 0; i < 4; i++)
#pragma unroll
            for (int j = 0; j < 4; j++)
                c[i][j] = fmaf(ar[i], br[j], c[i][j]);
    }

    float* op = out + ((size_t)b * 256 + o) * NPIX;
#pragma unroll
    for (int i = 0; i < 4; i++) {
        float4 v;
        v.x = c[i][0]; v.y = c[i][1]; v.z = c[i][2]; v.w = c[i][3];
        *(float4*)(op + (size_t)(ty * 4 + i) * 64 + tx * 4) = v;
    }
}

extern "C" void kernel_launch(void* const* d_in, const int* in_sizes, int n_in,
                              void* d_out, int out_size)
{
    const float* x  = (const float*)d_in[0];
    const float* wq = (const float*)d_in[1];
    const float* bq = (const float*)d_in[2];
    const float* wk = (const float*)d_in[3];
    const float* bk = (const float*)d_in[4];
    const float* wv = (const float*)d_in[5];
    const float* bv = (const float*)d_in[6];
    float* out = (float*)d_out;

    dim3 g1(NPIX / 64, 12, BATCH);   // 64 x 12 x 16 blocks
    qkv_gemm_kernel<<<g1, 256>>>(x, wq, bq, wk, bk, wv, bv);
    attn_kernel<<<BATCH * 256, 256>>>(out);
}

// round 3
// speedup vs baseline: 2.1773x; 2.1773x over previous
#include <cuda_runtime.h>
#include <cuda_bf16.h>
#include <cstdint>

#define BATCH 16
#define CIN   256
#define NPIX  4096   // 64*64
#define M3    768    // combined q,k,v output channels
#define KP    768    // split-K total (hi*hi + hi*lo + lo*hi)
#define KX    512    // x-split storage k length (hi 256 | lo 256)

// Scratch (device globals; no allocations allowed)
__device__ float         g_qkv[(size_t)BATCH * M3 * NPIX];        // 201 MB fp32 qkv
__device__ __nv_bfloat16 g_xs [(size_t)BATCH * NPIX * KX];        // 67 MB  x split, [b][p][kx]
__device__ __nv_bfloat16 g_ws [(size_t)M3 * KP];                  // 1.2 MB w split, [o][k']

__device__ __forceinline__ uint32_t s2u(const void* p) {
    uint32_t a;
    asm("{ .reg .u64 t; cvta.to.shared.u64 t, %1; cvt.u32.u64 %0, t; }" : "=r"(a) : "l"(p));
    return a;
}

#define SWZ(off) ((off) ^ (((off) >> 3) & 0x70))

__device__ __forceinline__ void cp_async16(uint32_t dst, const void* src) {
    asm volatile("cp.async.cg.shared.global [%0], [%1], 16;" :: "r"(dst), "l"(src));
}

__device__ __forceinline__ void ldmatrix_x4(uint32_t* r, uint32_t addr) {
    asm volatile("ldmatrix.sync.aligned.m8n8.x4.shared.b16 {%0,%1,%2,%3}, [%4];"
                 : "=r"(r[0]), "=r"(r[1]), "=r"(r[2]), "=r"(r[3]) : "r"(addr));
}

__device__ __forceinline__ void mma16816(float* c, const uint32_t* a, uint32_t b0, uint32_t b1) {
    asm volatile(
        "mma.sync.aligned.m16n8k16.row.col.f32.bf16.bf16.f32 "
        "{%0,%1,%2,%3}, {%4,%5,%6,%7}, {%8,%9}, {%0,%1,%2,%3};"
        : "+f"(c[0]), "+f"(c[1]), "+f"(c[2]), "+f"(c[3])
        : "r"(a[0]), "r"(a[1]), "r"(a[2]), "r"(a[3]), "r"(b0), "r"(b1));
}

// ---------------------------------------------------------------------------
// Kernel A: split x -> bf16 hi/lo, transposed to [b][p][kx] (kx: hi 0..255, lo 256..511)
// ---------------------------------------------------------------------------
__global__ __launch_bounds__(256) void split_x_kernel(const float* __restrict__ x) {
    __shared__ float s[64][65];
    const int b = blockIdx.z, c0 = blockIdx.y * 64, p0 = blockIdx.x * 64;
    const float* xb = x + ((size_t)b * CIN + c0) * NPIX + p0;
    const int t = threadIdx.x;
#pragma unroll
    for (int i = 0; i < 16; i++) {
        int idx = t + 256 * i;
        int c = idx >> 6, p = idx & 63;
        s[c][p] = xb[(size_t)c * NPIX + p];
    }
    __syncthreads();
    __nv_bfloat16* xs = g_xs + ((size_t)b * NPIX + p0) * KX + c0;
#pragma unroll
    for (int i = 0; i < 16; i++) {
        int idx = t + 256 * i;
        int cc = idx & 63, p = idx >> 6;
        float v = s[cc][p];
        __nv_bfloat16 h = __float2bfloat16(v);
        __nv_bfloat16 l = __float2bfloat16(v - __bfloat162float(h));
        xs[(size_t)p * KX + cc]       = h;
        xs[(size_t)p * KX + 256 + cc] = l;
    }
}

// ---------------------------------------------------------------------------
// Kernel B: split weights -> W' = [w_hi(256) | w_hi(256) | w_lo(256)] per row, [o][k']
// ---------------------------------------------------------------------------
__global__ __launch_bounds__(256) void split_w_kernel(
    const float* __restrict__ wq, const float* __restrict__ wk, const float* __restrict__ wv) {
    int idx = blockIdx.x * 256 + threadIdx.x;   // 768*768 total
    int o = idx / KP, kp = idx - o * KP;
    const float* w = (o < 256) ? wq : (o < 512) ? wk : wv;
    int ol = o & 255;
    int c  = (kp < 256) ? kp : (kp < 512) ? kp - 256 : kp - 512;
    float v = w[ol * CIN + c];
    __nv_bfloat16 h = __float2bfloat16(v);
    g_ws[idx] = (kp < 512) ? h : __float2bfloat16(v - __bfloat162float(h));
}

// ---------------------------------------------------------------------------
// Kernel C: HMMA bf16 GEMM.  C[o,p] = sum_k' W'[o,k'] * X'[p,k'] + bias
// CTA tile 128x128, BK=64 (128B SW128 rows), double-buffered cp.async.
// 256 threads = 8 warps (4 along M x 2 along N), warp tile 32x64.
// mma.sync.m16n8k16 bf16 -> fp32.
// ---------------------------------------------------------------------------
#define BM 128
#define BN 128
#define BK 64
#define NIT 12
#define STAGE_BYTES (BM * BK * 2 + BN * BK * 2)   // 32 KB (A then B)

extern __shared__ __align__(1024) char dynsmem[];

__global__ __launch_bounds__(256) void qkv_mma_kernel(
    const float* __restrict__ bq, const float* __restrict__ bk, const float* __restrict__ bv)
{
    const int t    = threadIdx.x;
    const int lane = t & 31;
    const int warp = t >> 5;
    const int wm   = warp & 3;     // 4 warps along M: 32 rows each
    const int wn   = warp >> 2;    // 2 warps along N: 64 cols each

    const int b  = blockIdx.z;
    const int o0 = blockIdx.y * BM;
    const int p0 = blockIdx.x * BN;

    const uint32_t smemBase = s2u(dynsmem);

    const __nv_bfloat16* Wb = g_ws + (size_t)o0 * KP;
    const __nv_bfloat16* Xb = g_xs + ((size_t)b * NPIX + p0) * KX;

    // cp.async tile fill: per stage, A = 1024 x 16B chunks, B = 1024 chunks.
    const int ld_row = t >> 1;          // not used; see loop below
    (void)ld_row;

    float c[2][8][4];
#pragma unroll
    for (int i = 0; i < 2; i++)
#pragma unroll
        for (int j = 0; j < 8; j++)
#pragma unroll
            for (int k = 0; k < 4; k++) c[i][j][k] = 0.f;

    auto load_stage = [&](int it, int s) {
        const int ka = it * BK;                              // W' col offset
        const int kb = (it < 8) ? it * BK : (it - 8) * BK;   // X' col remap
        const uint32_t aB = smemBase + s * STAGE_BYTES;
        const uint32_t bB = aB + BM * BK * 2;
#pragma unroll
        for (int j = 0; j < 4; j++) {
            int idx = t + 256 * j;          // 0..1023
            int row = idx >> 3, c16 = idx & 7;
            cp_async16(aB + SWZ(row * 128 + c16 * 16),
                       (const char*)(Wb + (size_t)row * KP + ka) + c16 * 16);
        }
#pragma unroll
        for (int j = 0; j < 4; j++) {
            int idx = t + 256 * j;
            int row = idx >> 3, c16 = idx & 7;
            cp_async16(bB + SWZ(row * 128 + c16 * 16),
                       (const char*)(Xb + (size_t)row * KX + kb) + c16 * 16);
        }
        asm volatile("cp.async.commit_group;");
    };

    auto compute_stage = [&](int s) {
        const uint32_t aB = smemBase + s * STAGE_BYTES;
        const uint32_t bB = aB + BM * BK * 2;
#pragma unroll
        for (int ks = 0; ks < 4; ks++) {
            uint32_t af[2][4];
#pragma unroll
            for (int mt = 0; mt < 2; mt++) {
                int row = wm * 32 + mt * 16 + (lane & 15);
                int col = ks * 32 + (lane >> 4) * 16;
                ldmatrix_x4(af[mt], aB + SWZ(row * 128 + col));
            }
            uint32_t bf[4][4];
#pragma unroll
            for (int np = 0; np < 4; np++) {
                int row = wn * 64 + np * 16 + (lane & 7) + ((lane >> 4) << 3);
                int col = ks * 32 + ((lane >> 3) & 1) * 16;
                ldmatrix_x4(bf[np], bB + SWZ(row * 128 + col));
            }
#pragma unroll
            for (int mt = 0; mt < 2; mt++)
#pragma unroll
                for (int np = 0; np < 4; np++) {
                    mma16816(c[mt][np * 2 + 0], af[mt], bf[np][0], bf[np][1]);
                    mma16816(c[mt][np * 2 + 1], af[mt], bf[np][2], bf[np][3]);
                }
        }
    };

    load_stage(0, 0);
    for (int it = 0; it < NIT; ++it) {
        if (it + 1 < NIT) load_stage(it + 1, (it + 1) & 1);
        if (it + 1 < NIT) asm volatile("cp.async.wait_group 1;" ::: "memory");
        else              asm volatile("cp.async.wait_group 0;" ::: "memory");
        __syncthreads();
        compute_stage(it & 1);
        __syncthreads();
    }

    // Epilogue: direct float2 stores with bias.
    float* outB = g_qkv + (size_t)b * M3 * NPIX;
#pragma unroll
    for (int mt = 0; mt < 2; mt++) {
        int r0 = o0 + wm * 32 + mt * 16 + (lane >> 2);
        int r1 = r0 + 8;
        const float* bp0 = (r0 < 256) ? bq : (r0 < 512) ? bk : bv;
        const float* bp1 = (r1 < 256) ? bq : (r1 < 512) ? bk : bv;
        float bias0 = bp0[r0 & 255];
        float bias1 = bp1[r1 & 255];
#pragma unroll
        for (int nt = 0; nt < 8; nt++) {
            int col = p0 + wn * 64 + nt * 8 + (lane & 3) * 2;
            float2 v0 = make_float2(c[mt][nt][0] + bias0, c[mt][nt][1] + bias0);
            float2 v1 = make_float2(c[mt][nt][2] + bias1, c[mt][nt][3] + bias1);
            *(float2*)(outB + (size_t)r0 * NPIX + col) = v0;
            *(float2*)(outB + (size_t)r1 * NPIX + col) = v1;
        }
    }
}

// ---------------------------------------------------------------------------
// Kernel D: attention (unchanged from round 1)
// ---------------------------------------------------------------------------
__global__ __launch_bounds__(256) void attn_kernel(float* __restrict__ out)
{
    __shared__ float X1[64][68];
    __shared__ float X2[64][68];

    const int blk = blockIdx.x;
    const int b   = blk >> 8;
    const int o   = blk & 255;

    const float* qp = g_qkv + ((size_t)b * M3 + o) * NPIX;
    const float* kp = qp + (size_t)256 * NPIX;
    const float* vp = qp + (size_t)512 * NPIX;

    const int t  = threadIdx.x;
    const int tx = t & 15;
    const int ty = t >> 4;

    float4 vr[4];
#pragma unroll
    for (int it = 0; it < 4; it++) {
        int flat = t * 4 + it * 1024;
        int h = flat >> 6, wcol = flat & 63;
        float4 qv = *(const float4*)(qp + flat);
        float4 kv = *(const float4*)(kp + flat);
        vr[it]    = *(const float4*)(vp + flat);
        X1[wcol + 0][h] = qv.x; X1[wcol + 1][h] = qv.y;
        X1[wcol + 2][h] = qv.z; X1[wcol + 3][h] = qv.w;
        X2[wcol + 0][h] = kv.x; X2[wcol + 1][h] = kv.y;
        X2[wcol + 2][h] = kv.z; X2[wcol + 3][h] = kv.w;
    }
    __syncthreads();

    float s[4][4] = {};
#pragma unroll 8
    for (int w = 0; w < 64; w++) {
        float4 a  = *(const float4*)(&X1[w][ty * 4]);
        float4 bb = *(const float4*)(&X2[w][tx * 4]);
        float ar[4] = {a.x, a.y, a.z, a.w};
        float br[4] = {bb.x, bb.y, bb.z, bb.w};
#pragma unroll
        for (int i = 0; i < 4; i++)
#pragma unroll
            for (int j = 0; j < 4; j++)
                s[i][j] = fmaf(ar[i], br[j], s[i][j]);
    }

    const float scale = 0.17677669529663687f;  // 1/sqrt(32)
#pragma unroll
    for (int i = 0; i < 4; i++) {
        float m = -1e30f;
#pragma unroll
        for (int j = 0; j < 4; j++) { s[i][j] *= scale; m = fmaxf(m, s[i][j]); }
#pragma unroll
        for (int off = 8; off > 0; off >>= 1)
            m = fmaxf(m, __shfl_xor_sync(0xffffffffu, m, off, 16));
        float sum = 0.f;
#pragma unroll
        for (int j = 0; j < 4; j++) { s[i][j] = __expf(s[i][j] - m); sum += s[i][j]; }
#pragma unroll
        for (int off = 8; off > 0; off >>= 1)
            sum += __shfl_xor_sync(0xffffffffu, sum, off, 16);
        float inv = 1.f / sum;
#pragma unroll
        for (int j = 0; j < 4; j++) s[i][j] *= inv;
    }

    __syncthreads();

#pragma unroll
    for (int i = 0; i < 4; i++)
#pragma unroll
        for (int j = 0; j < 4; j++)
            X1[tx * 4 + j][ty * 4 + i] = s[i][j];
#pragma unroll
    for (int it = 0; it < 4; it++) {
        int flat = t * 4 + it * 1024;
        int g = flat >> 6, wcol = flat & 63;
        *(float4*)(&X2[g][wcol]) = vr[it];
    }
    __syncthreads();

    float c[4][4] = {};
#pragma unroll 8
    for (int g = 0; g < 64; g++) {
        float4 a  = *(const float4*)(&X1[g][ty * 4]);
        float4 bb = *(const float4*)(&X2[g][tx * 4]);
        float ar[4] = {a.x, a.y, a.z, a.w};
        float br[4] = {bb.x, bb.y, bb.z, bb.w};
#pragma unroll
        for (int i = 0; i < 4; i++)
#pragma unroll
            for (int j = 0; j < 4; j++)
                c[i][j] = fmaf(ar[i], br[j], c[i][j]);
    }

    float* op = out + ((size_t)b * 256 + o) * NPIX;
#pragma unroll
    for (int i = 0; i < 4; i++) {
        float4 v;
        v.x = c[i][0]; v.y = c[i][1]; v.z = c[i][2]; v.w = c[i][3];
        *(float4*)(op + (size_t)(ty * 4 + i) * 64 + tx * 4) = v;
    }
}

extern "C" void kernel_launch(void* const* d_in, const int* in_sizes, int n_in,
                              void* d_out, int out_size)
{
    const float* x  = (const float*)d_in[0];
    const float* wq = (const float*)d_in[1];
    const float* bq = (const float*)d_in[2];
    const float* wk = (const float*)d_in[3];
    const float* bk = (const float*)d_in[4];
    const float* wv = (const float*)d_in[5];
    const float* bv = (const float*)d_in[6];
    float* out = (float*)d_out;

    cudaFuncSetAttribute(qkv_mma_kernel, cudaFuncAttributeMaxDynamicSharedMemorySize,
                         2 * STAGE_BYTES);

    split_x_kernel<<<dim3(NPIX / 64, CIN / 64, BATCH), 256>>>(x);
    split_w_kernel<<<(M3 * KP) / 256, 256>>>(wq, wk, wv);
    qkv_mma_kernel<<<dim3(NPIX / BN, M3 / BM, BATCH), 256, 2 * STAGE_BYTES>>>(bq, bk, bv);
    attn_kernel<<<BATCH * 256, 256>>>(out);
}